// round 2
// baseline (speedup 1.0000x reference)
#include <cuda_runtime.h>
#include <math.h>

#define BSZ  4
#define SEQ  4096
#define DIM  1024
#define NEXP 8
#define NTOK (BSZ*SEQ)   // 16384

// ---- scratch (device globals: allocation-free per harness rules) ----
__device__ float g_logits[(size_t)NTOK * DIM];   // 64 MB
__device__ int   g_cnt[NEXP];
__device__ int   g_tok[NEXP * NTOK];             // token lists per expert
__device__ float g_p[NTOK];

// =====================================================================
// Kernel 0: reset expert counters (graph-replay safe)
// =====================================================================
__global__ void k_init() {
    if (threadIdx.x < NEXP) g_cnt[threadIdx.x] = 0;
}

// =====================================================================
// Tiling for SGEMM: 128x128 block tile, BK=16, 256 threads, 8x8/thread
// =====================================================================
#define BM 128
#define BN 128
#define BK 16

// Kernel 1: gating GEMM  logits = x @ Wg + bg
// M = NTOK, N = K = DIM (all multiples of tile sizes -> no bounds checks)
__global__ __launch_bounds__(256) void k_gemm_gating(
    const float* __restrict__ A,      // x [NTOK, DIM]
    const float* __restrict__ B,      // Wg [DIM, DIM]
    const float* __restrict__ bias,   // bg [DIM]
    float* __restrict__ C)            // logits [NTOK, DIM]
{
    __shared__ float As[BK][BM];
    __shared__ float Bs[BK][BN];

    const int tid = threadIdx.x;
    const int tx = tid & 15;          // 0..15 -> n subtile
    const int ty = tid >> 4;          // 0..15 -> m subtile

    const int bm = blockIdx.y;
    const int bn = blockIdx.x;

    // A loads: tile is 128 rows x 16 cols = 512 float4 (4 per row)
    const int arow = tid >> 2;            // 0..63
    const int acol = (tid & 3) * 4;       // 0,4,8,12
    // B loads: tile is 16 rows x 128 cols = 512 float4 (32 per row)
    const int brow = tid >> 5;            // 0..7
    const int bcol = (tid & 31) * 4;      // 0..124

    const float* Ab = A + (size_t)bm * BM * DIM;
    const float* Bb = B + bn * BN;

    float acc[8][8];
    #pragma unroll
    for (int i = 0; i < 8; i++)
        #pragma unroll
        for (int j = 0; j < 8; j++) acc[i][j] = 0.f;

    for (int k0 = 0; k0 < DIM; k0 += BK) {
        float4 a0 = *(const float4*)(Ab + (size_t)arow        * DIM + k0 + acol);
        float4 a1 = *(const float4*)(Ab + (size_t)(arow + 64) * DIM + k0 + acol);
        float4 b0 = *(const float4*)(Bb + (size_t)(k0 + brow    ) * DIM + bcol);
        float4 b1 = *(const float4*)(Bb + (size_t)(k0 + brow + 8) * DIM + bcol);

        __syncthreads();   // previous iteration's reads done
        As[acol + 0][arow] = a0.x; As[acol + 1][arow] = a0.y;
        As[acol + 2][arow] = a0.z; As[acol + 3][arow] = a0.w;
        As[acol + 0][arow + 64] = a1.x; As[acol + 1][arow + 64] = a1.y;
        As[acol + 2][arow + 64] = a1.z; As[acol + 3][arow + 64] = a1.w;
        *(float4*)&Bs[brow    ][bcol] = b0;
        *(float4*)&Bs[brow + 8][bcol] = b1;
        __syncthreads();

        #pragma unroll
        for (int k = 0; k < BK; ++k) {
            float af[8], bf[8];
            *(float4*)(af    ) = *(const float4*)&As[k][ty * 8    ];
            *(float4*)(af + 4) = *(const float4*)&As[k][ty * 8 + 4];
            *(float4*)(bf    ) = *(const float4*)&Bs[k][tx * 8    ];
            *(float4*)(bf + 4) = *(const float4*)&Bs[k][tx * 8 + 4];
            #pragma unroll
            for (int i = 0; i < 8; i++)
                #pragma unroll
                for (int j = 0; j < 8; j++)
                    acc[i][j] = fmaf(af[i], bf[j], acc[i][j]);
        }
    }

    const int mbase = bm * BM + ty * 8;
    const int nbase = bn * BN + tx * 8;
    #pragma unroll
    for (int i = 0; i < 8; i++) {
        #pragma unroll
        for (int j4 = 0; j4 < 2; j4++) {
            float4 v;
            v.x = acc[i][j4*4+0] + bias[nbase + j4*4+0];
            v.y = acc[i][j4*4+1] + bias[nbase + j4*4+1];
            v.z = acc[i][j4*4+2] + bias[nbase + j4*4+2];
            v.w = acc[i][j4*4+3] + bias[nbase + j4*4+3];
            *(float4*)(C + (size_t)(mbase + i) * DIM + nbase + j4*4) = v;
        }
    }
}

// =====================================================================
// Kernel 2: per-token routing.  1 block (256 thr) per token.
// argmax with first-index tie break (matches jnp.argmax), p = 1/sum(exp)
// =====================================================================
__global__ __launch_bounds__(256) void k_route()
{
    const int t = blockIdx.x;
    const int tid = threadIdx.x;
    const float* row = g_logits + (size_t)t * DIM;

    float4 v = ((const float4*)row)[tid];

    float m = v.x; int mi = tid * 4;
    if (v.y > m) { m = v.y; mi = tid * 4 + 1; }
    if (v.z > m) { m = v.z; mi = tid * 4 + 2; }
    if (v.w > m) { m = v.w; mi = tid * 4 + 3; }

    // warp argmax (first index on tie)
    #pragma unroll
    for (int off = 16; off > 0; off >>= 1) {
        float om = __shfl_down_sync(0xffffffffu, m, off);
        int   oi = __shfl_down_sync(0xffffffffu, mi, off);
        if (om > m || (om == m && oi < mi)) { m = om; mi = oi; }
    }

    __shared__ float sm[8];
    __shared__ int   si[8];
    __shared__ float smax;
    __shared__ float ssum;
    __shared__ int   sarg;

    const int wid = tid >> 5, lane = tid & 31;
    if (lane == 0) { sm[wid] = m; si[wid] = mi; }
    __syncthreads();
    if (tid == 0) {
        float bm_ = sm[0]; int bi = si[0];
        #pragma unroll
        for (int w = 1; w < 8; w++) {
            if (sm[w] > bm_ || (sm[w] == bm_ && si[w] < bi)) { bm_ = sm[w]; bi = si[w]; }
        }
        smax = bm_; sarg = bi;
    }
    __syncthreads();

    const float mx = smax;
    float s = expf(v.x - mx) + expf(v.y - mx) + expf(v.z - mx) + expf(v.w - mx);
    #pragma unroll
    for (int off = 16; off > 0; off >>= 1)
        s += __shfl_down_sync(0xffffffffu, s, off);
    if (lane == 0) sm[wid] = s;
    __syncthreads();
    if (tid == 0) {
        float tot = 0.f;
        #pragma unroll
        for (int w = 0; w < 8; w++) tot += sm[w];
        ssum = tot;
        const int e = sarg & (NEXP - 1);
        const int pos = atomicAdd(&g_cnt[e], 1);
        g_tok[e * NTOK + pos] = t;
        g_p[t] = 1.f / tot;
    }
}

// =====================================================================
// Kernel 3: expert GEMM (gathered rows) + relu(+be)*p epilogue
// grid: (DIM/BN, NTOK/BM, NEXP)
// =====================================================================
__global__ __launch_bounds__(256) void k_gemm_expert(
    const float* __restrict__ X,      // [NTOK, DIM]
    const float* __restrict__ We,     // [NEXP, DIM, DIM]
    const float* __restrict__ be,     // [NEXP, DIM]
    float* __restrict__ Out)          // [NTOK, DIM]
{
    const int e = blockIdx.z;
    const int cnt = g_cnt[e];
    const int mbase = blockIdx.y * BM;
    if (mbase >= cnt) return;

    __shared__ float As[BK][BM];
    __shared__ float Bs[BK][BN];
    __shared__ int   stok[BM];

    const int tid = threadIdx.x;
    const int tx = tid & 15;
    const int ty = tid >> 4;
    const int bn = blockIdx.x;

    if (tid < BM) {
        const int i = mbase + tid;
        stok[tid] = (i < cnt) ? g_tok[e * NTOK + i] : -1;
    }
    __syncthreads();

    const int arow = tid >> 2;
    const int acol = (tid & 3) * 4;
    const int brow = tid >> 5;
    const int bcol = (tid & 31) * 4;

    const int tk0 = stok[arow];
    const int tk1 = stok[arow + 64];
    const float* Bb = We + (size_t)e * DIM * DIM + bn * BN;

    float acc[8][8];
    #pragma unroll
    for (int i = 0; i < 8; i++)
        #pragma unroll
        for (int j = 0; j < 8; j++) acc[i][j] = 0.f;

    for (int k0 = 0; k0 < DIM; k0 += BK) {
        float4 a0 = make_float4(0.f, 0.f, 0.f, 0.f);
        float4 a1 = make_float4(0.f, 0.f, 0.f, 0.f);
        if (tk0 >= 0) a0 = *(const float4*)(X + (size_t)tk0 * DIM + k0 + acol);
        if (tk1 >= 0) a1 = *(const float4*)(X + (size_t)tk1 * DIM + k0 + acol);
        float4 b0 = *(const float4*)(Bb + (size_t)(k0 + brow    ) * DIM + bcol);
        float4 b1 = *(const float4*)(Bb + (size_t)(k0 + brow + 8) * DIM + bcol);

        __syncthreads();
        As[acol + 0][arow] = a0.x; As[acol + 1][arow] = a0.y;
        As[acol + 2][arow] = a0.z; As[acol + 3][arow] = a0.w;
        As[acol + 0][arow + 64] = a1.x; As[acol + 1][arow + 64] = a1.y;
        As[acol + 2][arow + 64] = a1.z; As[acol + 3][arow + 64] = a1.w;
        *(float4*)&Bs[brow    ][bcol] = b0;
        *(float4*)&Bs[brow + 8][bcol] = b1;
        __syncthreads();

        #pragma unroll
        for (int k = 0; k < BK; ++k) {
            float af[8], bf[8];
            *(float4*)(af    ) = *(const float4*)&As[k][ty * 8    ];
            *(float4*)(af + 4) = *(const float4*)&As[k][ty * 8 + 4];
            *(float4*)(bf    ) = *(const float4*)&Bs[k][tx * 8    ];
            *(float4*)(bf + 4) = *(const float4*)&Bs[k][tx * 8 + 4];
            #pragma unroll
            for (int i = 0; i < 8; i++)
                #pragma unroll
                for (int j = 0; j < 8; j++)
                    acc[i][j] = fmaf(af[i], bf[j], acc[i][j]);
        }
    }

    const int nbase = bn * BN + tx * 8;
    const float* beb = be + e * DIM;
    #pragma unroll
    for (int i = 0; i < 8; i++) {
        const int tk = stok[ty * 8 + i];
        if (tk < 0) continue;
        const float pt = g_p[tk];
        #pragma unroll
        for (int j4 = 0; j4 < 2; j4++) {
            float4 v;
            v.x = fmaxf(acc[i][j4*4+0] + beb[nbase + j4*4+0], 0.f) * pt;
            v.y = fmaxf(acc[i][j4*4+1] + beb[nbase + j4*4+1], 0.f) * pt;
            v.z = fmaxf(acc[i][j4*4+2] + beb[nbase + j4*4+2], 0.f) * pt;
            v.w = fmaxf(acc[i][j4*4+3] + beb[nbase + j4*4+3], 0.f) * pt;
            *(float4*)(Out + (size_t)tk * DIM + nbase + j4*4) = v;
        }
    }
}

// =====================================================================
extern "C" void kernel_launch(void* const* d_in, const int* in_sizes, int n_in,
                              void* d_out, int out_size)
{
    const float* x  = (const float*)d_in[0];
    const float* Wg = (const float*)d_in[1];
    const float* bg = (const float*)d_in[2];
    const float* We = (const float*)d_in[3];
    const float* be = (const float*)d_in[4];
    float* out = (float*)d_out;

    float* logits;
    cudaGetSymbolAddress((void**)&logits, g_logits);

    k_init<<<1, 32>>>();
    k_gemm_gating<<<dim3(DIM / BN, NTOK / BM), 256>>>(x, Wg, bg, logits);
    k_route<<<NTOK, 256>>>();
    k_gemm_expert<<<dim3(DIM / BN, NTOK / BM, NEXP), 256>>>(x, We, be, out);
}

// round 4
// speedup vs baseline: 2.2881x; 2.2881x over previous
#include <cuda_runtime.h>
#include <cuda_fp16.h>
#include <math.h>
#include <stdint.h>

#define DIM  1024
#define NEXP 8
#define NTOK 16384
#define BM   128
#define BN   128
#define BK   32
#define KIT  (DIM/BK)        // 32 stages
#define ROWB 80              // bytes per smem row (32 halves data + 8 pad)
#define ARRB (128*ROWB)      // one array (128 rows)
#define STGB (4*ARRB)        // Ah|Al|Bh|Bl per stage = 40960 B
#define SMEM_BYTES (2*STGB)  // 81920

// ---------------- device-global scratch (allocation-free) ----------------
__device__ __half g_Xh[(size_t)NTOK * DIM];
__device__ __half g_Xl[(size_t)NTOK * DIM];
__device__ __half g_Wh[(size_t)(1 + NEXP) * DIM * DIM];   // [N][K], scaled x64
__device__ __half g_Wl[(size_t)(1 + NEXP) * DIM * DIM];
__device__ float  g_logits[(size_t)NTOK * DIM];
__device__ int    g_cnt[NEXP];
__device__ int    g_tok[NEXP * NTOK];
__device__ float  g_p[NTOK];

// ---------------- PTX helpers ----------------
static __device__ __forceinline__ uint32_t smem_u32(const void* p) {
    uint32_t a;
    asm("{ .reg .u64 t; cvta.to.shared.u64 t, %1; cvt.u32.u64 %0, t; }" : "=r"(a) : "l"(p));
    return a;
}
#define CP_ASYNC16(dst, src, sz) \
    asm volatile("cp.async.cg.shared.global [%0], [%1], 16, %2;" \
                 :: "r"(dst), "l"(src), "r"(sz) : "memory")
#define CP_COMMIT() asm volatile("cp.async.commit_group;" ::: "memory")
#define CP_WAIT1()  asm volatile("cp.async.wait_group 1;" ::: "memory")

#define LDM_X4(r, addr) \
    asm volatile("ldmatrix.sync.aligned.m8n8.x4.shared.b16 {%0,%1,%2,%3}, [%4];" \
                 : "=r"((r)[0]), "=r"((r)[1]), "=r"((r)[2]), "=r"((r)[3]) : "r"(addr))

#define MMA(d, a, b0_, b1_) \
    asm volatile("mma.sync.aligned.m16n8k16.row.col.f32.f16.f16.f32 " \
                 "{%0,%1,%2,%3},{%4,%5,%6,%7},{%8,%9},{%0,%1,%2,%3};" \
                 : "+f"((d)[0]), "+f"((d)[1]), "+f"((d)[2]), "+f"((d)[3]) \
                 : "r"((a)[0]), "r"((a)[1]), "r"((a)[2]), "r"((a)[3]), \
                   "r"(b0_), "r"(b1_))

// =====================================================================
__global__ void k_init() {
    if (threadIdx.x < NEXP) g_cnt[threadIdx.x] = 0;
}

// Split x into (h, l*4096) fp16 pairs. 4 floats / thread.
__global__ __launch_bounds__(256) void k_split_x(const float* __restrict__ X) {
    const size_t i = (size_t)blockIdx.x * 256 + threadIdx.x;   // float4 index
    float4 v = ((const float4*)X)[i];
    __half h0 = __float2half_rn(v.x), h1 = __float2half_rn(v.y);
    __half h2 = __float2half_rn(v.z), h3 = __float2half_rn(v.w);
    __half l0 = __float2half_rn((v.x - __half2float(h0)) * 4096.f);
    __half l1 = __float2half_rn((v.y - __half2float(h1)) * 4096.f);
    __half l2 = __float2half_rn((v.z - __half2float(h2)) * 4096.f);
    __half l3 = __float2half_rn((v.w - __half2float(h3)) * 4096.f);
    ((__half2*)g_Xh)[2 * i]     = __halves2half2(h0, h1);
    ((__half2*)g_Xh)[2 * i + 1] = __halves2half2(h2, h3);
    ((__half2*)g_Xl)[2 * i]     = __halves2half2(l0, l1);
    ((__half2*)g_Xl)[2 * i + 1] = __halves2half2(l2, l3);
}

// Transpose W ([K][N] -> [N][K]), scale x64, split to fp16 (h, l*4096).
__global__ __launch_bounds__(256) void k_split_w(const float* __restrict__ Wg,
                                                 const float* __restrict__ We) {
    __shared__ float t[32][33];
    const int z = blockIdx.z;
    const float* src = (z == 0) ? Wg : (We + (size_t)(z - 1) * DIM * DIM);
    __half* dh = g_Wh + (size_t)z * DIM * DIM;
    __half* dl = g_Wl + (size_t)z * DIM * DIM;
    const int x = blockIdx.x * 32 + threadIdx.x;
    const int y0 = blockIdx.y * 32 + threadIdx.y;
    #pragma unroll
    for (int i = 0; i < 32; i += 8)
        t[threadIdx.y + i][threadIdx.x] = src[(size_t)(y0 + i) * DIM + x];
    __syncthreads();
    const int x2 = blockIdx.y * 32 + threadIdx.x;
    const int y2 = blockIdx.x * 32 + threadIdx.y;
    #pragma unroll
    for (int i = 0; i < 32; i += 8) {
        float w6 = t[threadIdx.x][threadIdx.y + i] * 64.f;
        __half h = __float2half_rn(w6);
        __half l = __float2half_rn((w6 - __half2float(h)) * 4096.f);
        dh[(size_t)(y2 + i) * DIM + x2] = h;
        dl[(size_t)(y2 + i) * DIM + x2] = l;
    }
}

// =====================================================================
// GEMM via mma.sync fp16 split-precision (3 passes, 2 accumulators).
// MODE 0: gating  -> logits = x@Wg + bg
// MODE 1: expert  -> out = relu(x@We[e] + be[e]) * p   (rows gathered)
// =====================================================================
template <int MODE>
__global__ __launch_bounds__(256, 1) void k_gemm(const float* __restrict__ bias_,
                                                 float* __restrict__ C) {
    extern __shared__ char smem[];
    __shared__ int stok[BM];

    const int tid = threadIdx.x;
    const int lane = tid & 31;
    const int w = tid >> 5;
    const int mbase = blockIdx.y * BM;
    const int nbase = blockIdx.x * BN;

    int e = 0;
    const float* bias = bias_;
    size_t woff = 0;
    if (MODE == 1) {
        e = blockIdx.z;
        const int cnt = g_cnt[e];
        if (mbase >= cnt) return;
        woff = (size_t)(1 + e) * DIM * DIM;
        bias = bias_ + e * DIM;
        if (tid < BM) {
            const int i = mbase + tid;
            stok[tid] = (i < cnt) ? g_tok[e * NTOK + i] : -1;
        }
    } else {
        if (tid < BM) stok[tid] = mbase + tid;
    }
    __syncthreads();

    const uint32_t sb = smem_u32(smem);

    // ---- cp.async role: arr = tid>>6 (0 Ah, 1 Al, 2 Bh, 3 Bl); 2 rows each
    const int arr = tid >> 6;
    const int r0 = (tid & 63) << 1;
    const __half* gp[2];
    uint32_t sz[2];
    if (arr < 2) {
        const __half* base = (arr == 0) ? g_Xh : g_Xl;
        #pragma unroll
        for (int i = 0; i < 2; ++i) {
            const int tok = stok[r0 + i];
            sz[i] = (tok >= 0) ? 16u : 0u;
            gp[i] = base + (size_t)(tok >= 0 ? tok : 0) * DIM;
        }
    } else {
        const __half* base = ((arr == 2) ? g_Wh : g_Wl) + woff;
        #pragma unroll
        for (int i = 0; i < 2; ++i) {
            gp[i] = base + (size_t)(nbase + r0 + i) * DIM;
            sz[i] = 16u;
        }
    }
    const uint32_t sdst = sb + arr * ARRB + r0 * ROWB;

    // ---- warp tiling: 8 warps as 2(m) x 4(n); warp tile 64x32
    const int wm = (w >> 2) * 64;
    const int wn = (w & 3) * 32;
    const int lr = lane & 15;
    const int lkb = (lane >> 4) * 16;   // k-half byte offset for ldmatrix

    float acc1[4][4][4];
    float acc2[4][4][4];
    #pragma unroll
    for (int mi = 0; mi < 4; ++mi)
        #pragma unroll
        for (int nj = 0; nj < 4; ++nj)
            #pragma unroll
            for (int q = 0; q < 4; ++q) { acc1[mi][nj][q] = 0.f; acc2[mi][nj][q] = 0.f; }

    // prologue: stage 0
    #pragma unroll
    for (int i = 0; i < 2; ++i)
        #pragma unroll
        for (int q = 0; q < 4; ++q)
            CP_ASYNC16(sdst + i * ROWB + q * 16, (const char*)gp[i] + q * 16, sz[i]);
    CP_COMMIT();

    for (int it = 0; it < KIT; ++it) {
        const uint32_t sgb = sb + (it & 1) * STGB;
        if (it + 1 < KIT) {
            const uint32_t d = sdst + ((it + 1) & 1) * STGB;
            const int k0 = (it + 1) * BK;
            #pragma unroll
            for (int i = 0; i < 2; ++i)
                #pragma unroll
                for (int q = 0; q < 4; ++q)
                    CP_ASYNC16(d + i * ROWB + q * 16,
                               (const char*)(gp[i] + k0) + q * 16, sz[i]);
        }
        CP_COMMIT();
        CP_WAIT1();
        __syncthreads();

        #pragma unroll
        for (int kk = 0; kk < 2; ++kk) {       // two k16 steps in BK=32
            const uint32_t kb = kk * 32 + lkb; // byte offset within row
            uint32_t ah[4][4], al[4][4];
            #pragma unroll
            for (int mi = 0; mi < 4; ++mi) {
                const uint32_t rowo = (uint32_t)(wm + mi * 16 + lr) * ROWB + kb;
                LDM_X4(ah[mi], sgb + rowo);            // Ah at arr 0
                LDM_X4(al[mi], sgb + ARRB + rowo);     // Al at arr 1
            }
            #pragma unroll
            for (int njp = 0; njp < 2; ++njp) {
                uint32_t bh[4], bl[4];
                const uint32_t rowo = (uint32_t)(wn + njp * 16 + lr) * ROWB + kb;
                LDM_X4(bh, sgb + 2 * ARRB + rowo);
                LDM_X4(bl, sgb + 3 * ARRB + rowo);
                #pragma unroll
                for (int mi = 0; mi < 4; ++mi) {
                    #pragma unroll
                    for (int t = 0; t < 2; ++t) {
                        const int nj = njp * 2 + t;
                        MMA(acc1[mi][nj], ah[mi], bh[t], bh[t + 2]);
                        MMA(acc2[mi][nj], ah[mi], bl[t], bl[t + 2]);
                        MMA(acc2[mi][nj], al[mi], bh[t], bh[t + 2]);
                    }
                }
            }
        }
        __syncthreads();
    }

    // ---- epilogue ----
    const int gid = lane >> 2;
    const int tq = lane & 3;
    #pragma unroll
    for (int mi = 0; mi < 4; ++mi) {
        #pragma unroll
        for (int rh = 0; rh < 2; ++rh) {
            const int mloc = wm + mi * 16 + gid + rh * 8;
            const int tok = stok[mloc];
            if (MODE == 1 && tok < 0) continue;
            const float pt = (MODE == 1) ? g_p[tok] : 1.f;
            float* dst = C + (size_t)tok * DIM;
            #pragma unroll
            for (int nj = 0; nj < 4; ++nj) {
                const int n = nbase + wn + nj * 8 + tq * 2;
                float v0 = (acc1[mi][nj][rh * 2]     + acc2[mi][nj][rh * 2]     * (1.f / 4096.f)) * (1.f / 64.f) + bias[n];
                float v1 = (acc1[mi][nj][rh * 2 + 1] + acc2[mi][nj][rh * 2 + 1] * (1.f / 4096.f)) * (1.f / 64.f) + bias[n + 1];
                if (MODE == 1) {
                    v0 = fmaxf(v0, 0.f) * pt;
                    v1 = fmaxf(v1, 0.f) * pt;
                }
                *(float2*)(dst + n) = make_float2(v0, v1);
            }
        }
    }
}

// =====================================================================
// Routing: 1 block per token; argmax (first-index tie-break) + 1/sum(exp)
// =====================================================================
__global__ __launch_bounds__(256) void k_route() {
    const int t = blockIdx.x;
    const int tid = threadIdx.x;
    const float* row = g_logits + (size_t)t * DIM;

    float4 v = ((const float4*)row)[tid];

    float m = v.x; int mi = tid * 4;
    if (v.y > m) { m = v.y; mi = tid * 4 + 1; }
    if (v.z > m) { m = v.z; mi = tid * 4 + 2; }
    if (v.w > m) { m = v.w; mi = tid * 4 + 3; }

    #pragma unroll
    for (int off = 16; off > 0; off >>= 1) {
        float om = __shfl_down_sync(0xffffffffu, m, off);
        int   oi = __shfl_down_sync(0xffffffffu, mi, off);
        if (om > m || (om == m && oi < mi)) { m = om; mi = oi; }
    }

    __shared__ float sm[8];
    __shared__ int   si[8];
    __shared__ float smax;
    __shared__ int   sarg;

    const int wid = tid >> 5, lane = tid & 31;
    if (lane == 0) { sm[wid] = m; si[wid] = mi; }
    __syncthreads();
    if (tid == 0) {
        float bm_ = sm[0]; int bi = si[0];
        #pragma unroll
        for (int w = 1; w < 8; w++)
            if (sm[w] > bm_ || (sm[w] == bm_ && si[w] < bi)) { bm_ = sm[w]; bi = si[w]; }
        smax = bm_; sarg = bi;
    }
    __syncthreads();

    const float mx = smax;
    float s = expf(v.x - mx) + expf(v.y - mx) + expf(v.z - mx) + expf(v.w - mx);
    #pragma unroll
    for (int off = 16; off > 0; off >>= 1)
        s += __shfl_down_sync(0xffffffffu, s, off);
    if (lane == 0) sm[wid] = s;
    __syncthreads();
    if (tid == 0) {
        float tot = 0.f;
        #pragma unroll
        for (int w = 0; w < 8; w++) tot += sm[w];
        const int ex = sarg & (NEXP - 1);
        const int pos = atomicAdd(&g_cnt[ex], 1);
        g_tok[ex * NTOK + pos] = t;
        g_p[t] = 1.f / tot;
    }
}

// =====================================================================
extern "C" void kernel_launch(void* const* d_in, const int* in_sizes, int n_in,
                              void* d_out, int out_size) {
    const float* x  = (const float*)d_in[0];
    const float* Wg = (const float*)d_in[1];
    const float* bg = (const float*)d_in[2];
    const float* We = (const float*)d_in[3];
    const float* be = (const float*)d_in[4];
    float* out = (float*)d_out;

    float* logits;
    cudaGetSymbolAddress((void**)&logits, g_logits);

    cudaFuncSetAttribute(k_gemm<0>, cudaFuncAttributeMaxDynamicSharedMemorySize, SMEM_BYTES);
    cudaFuncSetAttribute(k_gemm<1>, cudaFuncAttributeMaxDynamicSharedMemorySize, SMEM_BYTES);

    k_init<<<1, 32>>>();
    k_split_x<<<(NTOK * DIM / 4) / 256, 256>>>(x);
    k_split_w<<<dim3(32, 32, 1 + NEXP), dim3(32, 8)>>>(Wg, We);
    k_gemm<0><<<dim3(DIM / BN, NTOK / BM), 256, SMEM_BYTES>>>(bg, logits);
    k_route<<<NTOK, 256>>>();
    k_gemm<1><<<dim3(DIM / BN, NTOK / BM, NEXP), 256, SMEM_BYTES>>>(be, out);
}

// round 5
// speedup vs baseline: 2.3423x; 1.0237x over previous
#include <cuda_runtime.h>
#include <cuda_fp16.h>
#include <math.h>
#include <stdint.h>

#define DIM  1024
#define NEXP 8
#define NTOK 16384
#define BM   128
#define BN   128
#define BK   32
#define KIT  (DIM/BK)        // 32 stages
#define ROWB 80              // bytes per smem row (32 halves data + 8 pad)
#define ARRB (128*ROWB)      // one array (128 rows)
#define STGB (4*ARRB)        // Ah|Al|Bh|Bl per stage = 40960 B
#define SMEM_BYTES (2*STGB)  // 81920

// ---------------- device-global scratch (allocation-free) ----------------
__device__ __half g_Xh[(size_t)NTOK * DIM];
__device__ __half g_Xl[(size_t)NTOK * DIM];
__device__ __half g_Wh[(size_t)(1 + NEXP) * DIM * DIM];   // [N][K], scaled x64
__device__ __half g_Wl[(size_t)(1 + NEXP) * DIM * DIM];
__device__ float  g_logits[(size_t)NTOK * DIM];
__device__ int    g_cnt[NEXP];
__device__ int    g_tok[NEXP * NTOK];
__device__ float  g_p[NTOK];

// ---------------- PTX helpers ----------------
static __device__ __forceinline__ uint32_t smem_u32(const void* p) {
    uint32_t a;
    asm("{ .reg .u64 t; cvta.to.shared.u64 t, %1; cvt.u32.u64 %0, t; }" : "=r"(a) : "l"(p));
    return a;
}
#define CP_ASYNC16(dst, src, sz) \
    asm volatile("cp.async.cg.shared.global [%0], [%1], 16, %2;" \
                 :: "r"(dst), "l"(src), "r"(sz) : "memory")
#define CP_COMMIT() asm volatile("cp.async.commit_group;" ::: "memory")
#define CP_WAIT1()  asm volatile("cp.async.wait_group 1;" ::: "memory")

#define LDM_X4(r, addr) \
    asm volatile("ldmatrix.sync.aligned.m8n8.x4.shared.b16 {%0,%1,%2,%3}, [%4];" \
                 : "=r"((r)[0]), "=r"((r)[1]), "=r"((r)[2]), "=r"((r)[3]) : "r"(addr))

#define MMA(d, a, b0_, b1_) \
    asm volatile("mma.sync.aligned.m16n8k16.row.col.f32.f16.f16.f32 " \
                 "{%0,%1,%2,%3},{%4,%5,%6,%7},{%8,%9},{%0,%1,%2,%3};" \
                 : "+f"((d)[0]), "+f"((d)[1]), "+f"((d)[2]), "+f"((d)[3]) \
                 : "r"((a)[0]), "r"((a)[1]), "r"((a)[2]), "r"((a)[3]), \
                   "r"(b0_), "r"(b1_))

// =====================================================================
__global__ void k_init() {
    if (threadIdx.x < NEXP) g_cnt[threadIdx.x] = 0;
}

// Split x into (h, l*4096) fp16 pairs. 4 floats / thread.
__global__ __launch_bounds__(256) void k_split_x(const float* __restrict__ X) {
    const size_t i = (size_t)blockIdx.x * 256 + threadIdx.x;   // float4 index
    float4 v = ((const float4*)X)[i];
    __half h0 = __float2half_rn(v.x), h1 = __float2half_rn(v.y);
    __half h2 = __float2half_rn(v.z), h3 = __float2half_rn(v.w);
    __half l0 = __float2half_rn((v.x - __half2float(h0)) * 4096.f);
    __half l1 = __float2half_rn((v.y - __half2float(h1)) * 4096.f);
    __half l2 = __float2half_rn((v.z - __half2float(h2)) * 4096.f);
    __half l3 = __float2half_rn((v.w - __half2float(h3)) * 4096.f);
    ((__half2*)g_Xh)[2 * i]     = __halves2half2(h0, h1);
    ((__half2*)g_Xh)[2 * i + 1] = __halves2half2(h2, h3);
    ((__half2*)g_Xl)[2 * i]     = __halves2half2(l0, l1);
    ((__half2*)g_Xl)[2 * i + 1] = __halves2half2(l2, l3);
}

// Transpose W ([K][N] -> [N][K]), scale x64, split to fp16 (h, l*4096).
__global__ __launch_bounds__(256) void k_split_w(const float* __restrict__ Wg,
                                                 const float* __restrict__ We) {
    __shared__ float t[32][33];
    const int z = blockIdx.z;
    const float* src = (z == 0) ? Wg : (We + (size_t)(z - 1) * DIM * DIM);
    __half* dh = g_Wh + (size_t)z * DIM * DIM;
    __half* dl = g_Wl + (size_t)z * DIM * DIM;
    const int x = blockIdx.x * 32 + threadIdx.x;
    const int y0 = blockIdx.y * 32 + threadIdx.y;
    #pragma unroll
    for (int i = 0; i < 32; i += 8)
        t[threadIdx.y + i][threadIdx.x] = src[(size_t)(y0 + i) * DIM + x];
    __syncthreads();
    const int x2 = blockIdx.y * 32 + threadIdx.x;
    const int y2 = blockIdx.x * 32 + threadIdx.y;
    #pragma unroll
    for (int i = 0; i < 32; i += 8) {
        float w6 = t[threadIdx.x][threadIdx.y + i] * 64.f;
        __half h = __float2half_rn(w6);
        __half l = __float2half_rn((w6 - __half2float(h)) * 4096.f);
        dh[(size_t)(y2 + i) * DIM + x2] = h;
        dl[(size_t)(y2 + i) * DIM + x2] = l;
    }
}

// =====================================================================
// GEMM via mma.sync fp16 split-precision (3 passes, 2 accumulators).
// 512 threads, 16 warps as 4(m) x 4(n), warp tile 32x32.
// MODE 0: gating  -> logits = x@Wg + bg
// MODE 1: expert  -> out = relu(x@We[e] + be[e]) * p   (rows gathered)
// =====================================================================
template <int MODE>
__global__ __launch_bounds__(512, 1) void k_gemm(const float* __restrict__ bias_,
                                                 float* __restrict__ C) {
    extern __shared__ char smem[];
    __shared__ int stok[BM];

    const int tid = threadIdx.x;
    const int lane = tid & 31;
    const int w = tid >> 5;
    const int mbase = blockIdx.y * BM;
    const int nbase = blockIdx.x * BN;

    int e = 0;
    const float* bias = bias_;
    size_t woff = 0;
    if (MODE == 1) {
        e = blockIdx.z;
        const int cnt = g_cnt[e];
        if (mbase >= cnt) return;
        woff = (size_t)(1 + e) * DIM * DIM;
        bias = bias_ + e * DIM;
        if (tid < BM) {
            const int i = mbase + tid;
            stok[tid] = (i < cnt) ? g_tok[e * NTOK + i] : -1;
        }
    } else {
        if (tid < BM) stok[tid] = mbase + tid;
    }
    __syncthreads();

    const uint32_t sb = smem_u32(smem);

    // ---- cp.async role: arr = tid>>7 (0 Ah, 1 Al, 2 Bh, 3 Bl); 1 row each
    const int arr = tid >> 7;
    const int r0 = tid & 127;
    const __half* gp;
    uint32_t sz;
    if (arr < 2) {
        const __half* base = (arr == 0) ? g_Xh : g_Xl;
        const int tok = stok[r0];
        sz = (tok >= 0) ? 16u : 0u;
        gp = base + (size_t)(tok >= 0 ? tok : 0) * DIM;
    } else {
        const __half* base = ((arr == 2) ? g_Wh : g_Wl) + woff;
        gp = base + (size_t)(nbase + r0) * DIM;
        sz = 16u;
    }
    const uint32_t sdst = sb + arr * ARRB + r0 * ROWB;

    // ---- warp tiling: 16 warps as 4(m) x 4(n); warp tile 32x32
    const int wm = (w & 3) * 32;
    const int wn = (w >> 2) * 32;
    const int lr = lane & 15;
    const int lkb = (lane >> 4) * 16;   // k-half byte offset for ldmatrix

    float acc1[2][4][4];
    float acc2[2][4][4];
    #pragma unroll
    for (int mi = 0; mi < 2; ++mi)
        #pragma unroll
        for (int nj = 0; nj < 4; ++nj)
            #pragma unroll
            for (int q = 0; q < 4; ++q) { acc1[mi][nj][q] = 0.f; acc2[mi][nj][q] = 0.f; }

    // prologue: stage 0
    #pragma unroll
    for (int q = 0; q < 4; ++q)
        CP_ASYNC16(sdst + q * 16, (const char*)gp + q * 16, sz);
    CP_COMMIT();

    for (int it = 0; it < KIT; ++it) {
        const uint32_t sgb = sb + (it & 1) * STGB;
        if (it + 1 < KIT) {
            const uint32_t d = sdst + ((it + 1) & 1) * STGB;
            const int k0 = (it + 1) * BK;
            #pragma unroll
            for (int q = 0; q < 4; ++q)
                CP_ASYNC16(d + q * 16, (const char*)(gp + k0) + q * 16, sz);
        }
        CP_COMMIT();
        CP_WAIT1();
        __syncthreads();

        #pragma unroll
        for (int kk = 0; kk < 2; ++kk) {       // two k16 steps in BK=32
            const uint32_t kb = kk * 32 + lkb; // byte offset within row
            uint32_t ah[2][4], al[2][4];
            #pragma unroll
            for (int mi = 0; mi < 2; ++mi) {
                const uint32_t rowo = (uint32_t)(wm + mi * 16 + lr) * ROWB + kb;
                LDM_X4(ah[mi], sgb + rowo);            // Ah at arr 0
                LDM_X4(al[mi], sgb + ARRB + rowo);     // Al at arr 1
            }
            #pragma unroll
            for (int njp = 0; njp < 2; ++njp) {
                uint32_t bh[4], bl[4];
                const uint32_t rowo = (uint32_t)(wn + njp * 16 + lr) * ROWB + kb;
                LDM_X4(bh, sgb + 2 * ARRB + rowo);
                LDM_X4(bl, sgb + 3 * ARRB + rowo);
                #pragma unroll
                for (int mi = 0; mi < 2; ++mi) {
                    #pragma unroll
                    for (int t = 0; t < 2; ++t) {
                        const int nj = njp * 2 + t;
                        MMA(acc1[mi][nj], ah[mi], bh[t], bh[t + 2]);
                        MMA(acc2[mi][nj], ah[mi], bl[t], bl[t + 2]);
                        MMA(acc2[mi][nj], al[mi], bh[t], bh[t + 2]);
                    }
                }
            }
        }
        __syncthreads();
    }

    // ---- epilogue ----
    const int gid = lane >> 2;
    const int tq = lane & 3;
    #pragma unroll
    for (int mi = 0; mi < 2; ++mi) {
        #pragma unroll
        for (int rh = 0; rh < 2; ++rh) {
            const int mloc = wm + mi * 16 + gid + rh * 8;
            const int tok = stok[mloc];
            if (MODE == 1 && tok < 0) continue;
            const float pt = (MODE == 1) ? g_p[tok] : 1.f;
            float* dst = C + (size_t)tok * DIM;
            #pragma unroll
            for (int nj = 0; nj < 4; ++nj) {
                const int n = nbase + wn + nj * 8 + tq * 2;
                float v0 = (acc1[mi][nj][rh * 2]     + acc2[mi][nj][rh * 2]     * (1.f / 4096.f)) * (1.f / 64.f) + bias[n];
                float v1 = (acc1[mi][nj][rh * 2 + 1] + acc2[mi][nj][rh * 2 + 1] * (1.f / 4096.f)) * (1.f / 64.f) + bias[n + 1];
                if (MODE == 1) {
                    v0 = fmaxf(v0, 0.f) * pt;
                    v1 = fmaxf(v1, 0.f) * pt;
                }
                *(float2*)(dst + n) = make_float2(v0, v1);
            }
        }
    }
}

// =====================================================================
// Routing: 1 block per token; argmax (first-index tie-break) + 1/sum(exp)
// =====================================================================
__global__ __launch_bounds__(256) void k_route() {
    const int t = blockIdx.x;
    const int tid = threadIdx.x;
    const float* row = g_logits + (size_t)t * DIM;

    float4 v = ((const float4*)row)[tid];

    float m = v.x; int mi = tid * 4;
    if (v.y > m) { m = v.y; mi = tid * 4 + 1; }
    if (v.z > m) { m = v.z; mi = tid * 4 + 2; }
    if (v.w > m) { m = v.w; mi = tid * 4 + 3; }

    #pragma unroll
    for (int off = 16; off > 0; off >>= 1) {
        float om = __shfl_down_sync(0xffffffffu, m, off);
        int   oi = __shfl_down_sync(0xffffffffu, mi, off);
        if (om > m || (om == m && oi < mi)) { m = om; mi = oi; }
    }

    __shared__ float sm[8];
    __shared__ int   si[8];
    __shared__ float smax;
    __shared__ int   sarg;

    const int wid = tid >> 5, lane = tid & 31;
    if (lane == 0) { sm[wid] = m; si[wid] = mi; }
    __syncthreads();
    if (tid == 0) {
        float bm_ = sm[0]; int bi = si[0];
        #pragma unroll
        for (int w = 1; w < 8; w++)
            if (sm[w] > bm_ || (sm[w] == bm_ && si[w] < bi)) { bm_ = sm[w]; bi = si[w]; }
        smax = bm_; sarg = bi;
    }
    __syncthreads();

    const float mx = smax;
    float s = expf(v.x - mx) + expf(v.y - mx) + expf(v.z - mx) + expf(v.w - mx);
    #pragma unroll
    for (int off = 16; off > 0; off >>= 1)
        s += __shfl_down_sync(0xffffffffu, s, off);
    if (lane == 0) sm[wid] = s;
    __syncthreads();
    if (tid == 0) {
        float tot = 0.f;
        #pragma unroll
        for (int w = 0; w < 8; w++) tot += sm[w];
        const int ex = sarg & (NEXP - 1);
        const int pos = atomicAdd(&g_cnt[ex], 1);
        g_tok[ex * NTOK + pos] = t;
        g_p[t] = 1.f / tot;
    }
}

// =====================================================================
extern "C" void kernel_launch(void* const* d_in, const int* in_sizes, int n_in,
                              void* d_out, int out_size) {
    const float* x  = (const float*)d_in[0];
    const float* Wg = (const float*)d_in[1];
    const float* bg = (const float*)d_in[2];
    const float* We = (const float*)d_in[3];
    const float* be = (const float*)d_in[4];
    float* out = (float*)d_out;

    float* logits;
    cudaGetSymbolAddress((void**)&logits, g_logits);

    cudaFuncSetAttribute(k_gemm<0>, cudaFuncAttributeMaxDynamicSharedMemorySize, SMEM_BYTES);
    cudaFuncSetAttribute(k_gemm<1>, cudaFuncAttributeMaxDynamicSharedMemorySize, SMEM_BYTES);

    k_init<<<1, 32>>>();
    k_split_x<<<(NTOK * DIM / 4) / 256, 256>>>(x);
    k_split_w<<<dim3(32, 32, 1 + NEXP), dim3(32, 8)>>>(Wg, We);
    k_gemm<0><<<dim3(DIM / BN, NTOK / BM), 512, SMEM_BYTES>>>(bg, logits);
    k_route<<<NTOK, 256>>>();
    k_gemm<1><<<dim3(DIM / BN, NTOK / BM, NEXP), 512, SMEM_BYTES>>>(be, out);
}

// round 6
// speedup vs baseline: 2.5127x; 1.0727x over previous
#include <cuda_runtime.h>
#include <cuda_fp16.h>
#include <math.h>
#include <stdint.h>

#define DIM  1024
#define NEXP 8
#define NTOK 16384
#define BM   128
#define BN   128
#define BK   32
#define KIT  (DIM/BK)        // 32 stages
#define ROWB 80              // bytes per smem row (32 halves data + 8 pad)
#define ARRB (128*ROWB)      // one array (128 rows)
#define STGB (4*ARRB)        // Ah|Al|Bh|Bl per stage = 40960 B
#define NSTG 3
#define SMEM_BYTES (NSTG*STGB)  // 122880

// ---------------- device-global scratch (allocation-free) ----------------
__device__ __half g_Xh[(size_t)NTOK * DIM];
__device__ __half g_Xl[(size_t)NTOK * DIM];
__device__ __half g_Wh[(size_t)(1 + NEXP) * DIM * DIM];   // [N][K], scaled x64
__device__ __half g_Wl[(size_t)(1 + NEXP) * DIM * DIM];
__device__ float  g_logits[(size_t)NTOK * DIM];
__device__ int    g_cnt[NEXP];
__device__ int    g_tok[NEXP * NTOK];
__device__ float  g_p[NTOK];

// ---------------- PTX helpers ----------------
static __device__ __forceinline__ uint32_t smem_u32(const void* p) {
    uint32_t a;
    asm("{ .reg .u64 t; cvta.to.shared.u64 t, %1; cvt.u32.u64 %0, t; }" : "=r"(a) : "l"(p));
    return a;
}
#define CP_ASYNC16(dst, src, sz) \
    asm volatile("cp.async.cg.shared.global [%0], [%1], 16, %2;" \
                 :: "r"(dst), "l"(src), "r"(sz) : "memory")
#define CP_COMMIT() asm volatile("cp.async.commit_group;" ::: "memory")
#define CP_WAIT_1() asm volatile("cp.async.wait_group 1;" ::: "memory")

#define LDM_X4(r, addr) \
    asm volatile("ldmatrix.sync.aligned.m8n8.x4.shared.b16 {%0,%1,%2,%3}, [%4];" \
                 : "=r"((r)[0]), "=r"((r)[1]), "=r"((r)[2]), "=r"((r)[3]) : "r"(addr))

#define MMA(d, a, b0_, b1_) \
    asm volatile("mma.sync.aligned.m16n8k16.row.col.f32.f16.f16.f32 " \
                 "{%0,%1,%2,%3},{%4,%5,%6,%7},{%8,%9},{%0,%1,%2,%3};" \
                 : "+f"((d)[0]), "+f"((d)[1]), "+f"((d)[2]), "+f"((d)[3]) \
                 : "r"((a)[0]), "r"((a)[1]), "r"((a)[2]), "r"((a)[3]), \
                   "r"(b0_), "r"(b1_))

// =====================================================================
__global__ void k_init() {
    if (threadIdx.x < NEXP) g_cnt[threadIdx.x] = 0;
}

// Split x into (h, l*4096) fp16 pairs. 4 floats / thread.
__global__ __launch_bounds__(256) void k_split_x(const float* __restrict__ X) {
    const size_t i = (size_t)blockIdx.x * 256 + threadIdx.x;   // float4 index
    float4 v = ((const float4*)X)[i];
    __half h0 = __float2half_rn(v.x), h1 = __float2half_rn(v.y);
    __half h2 = __float2half_rn(v.z), h3 = __float2half_rn(v.w);
    __half l0 = __float2half_rn((v.x - __half2float(h0)) * 4096.f);
    __half l1 = __float2half_rn((v.y - __half2float(h1)) * 4096.f);
    __half l2 = __float2half_rn((v.z - __half2float(h2)) * 4096.f);
    __half l3 = __float2half_rn((v.w - __half2float(h3)) * 4096.f);
    ((__half2*)g_Xh)[2 * i]     = __halves2half2(h0, h1);
    ((__half2*)g_Xh)[2 * i + 1] = __halves2half2(h2, h3);
    ((__half2*)g_Xl)[2 * i]     = __halves2half2(l0, l1);
    ((__half2*)g_Xl)[2 * i + 1] = __halves2half2(l2, l3);
}

// Transpose W ([K][N] -> [N][K]), scale x64, split to fp16 (h, l*4096).
__global__ __launch_bounds__(256) void k_split_w(const float* __restrict__ Wg,
                                                 const float* __restrict__ We) {
    __shared__ float t[32][33];
    const int z = blockIdx.z;
    const float* src = (z == 0) ? Wg : (We + (size_t)(z - 1) * DIM * DIM);
    __half* dh = g_Wh + (size_t)z * DIM * DIM;
    __half* dl = g_Wl + (size_t)z * DIM * DIM;
    const int x = blockIdx.x * 32 + threadIdx.x;
    const int y0 = blockIdx.y * 32 + threadIdx.y;
    #pragma unroll
    for (int i = 0; i < 32; i += 8)
        t[threadIdx.y + i][threadIdx.x] = src[(size_t)(y0 + i) * DIM + x];
    __syncthreads();
    const int x2 = blockIdx.y * 32 + threadIdx.x;
    const int y2 = blockIdx.x * 32 + threadIdx.y;
    #pragma unroll
    for (int i = 0; i < 32; i += 8) {
        float w6 = t[threadIdx.x][threadIdx.y + i] * 64.f;
        __half h = __float2half_rn(w6);
        __half l = __float2half_rn((w6 - __half2float(h)) * 4096.f);
        dh[(size_t)(y2 + i) * DIM + x2] = h;
        dl[(size_t)(y2 + i) * DIM + x2] = l;
    }
}

// =====================================================================
// GEMM via mma.sync fp16 split-precision (3 passes, 2 accumulators).
// 512 threads, 16 warps as 4(m) x 4(n), warp tile 32x32.
// 3-stage cp.async pipeline, ONE __syncthreads per stage.
// MODE 0: gating  -> logits = x@Wg + bg
// MODE 1: expert  -> out = relu(x@We[e] + be[e]) * p   (rows gathered)
// =====================================================================
template <int MODE>
__global__ __launch_bounds__(512, 1) void k_gemm(const float* __restrict__ bias_,
                                                 float* __restrict__ C) {
    extern __shared__ char smem[];
    __shared__ int stok[BM];

    const int tid = threadIdx.x;
    const int lane = tid & 31;
    const int w = tid >> 5;
    const int mbase = blockIdx.y * BM;
    const int nbase = blockIdx.x * BN;

    int e = 0;
    const float* bias = bias_;
    size_t woff = 0;
    if (MODE == 1) {
        e = blockIdx.z;
        const int cnt = g_cnt[e];
        if (mbase >= cnt) return;
        woff = (size_t)(1 + e) * DIM * DIM;
        bias = bias_ + e * DIM;
        if (tid < BM) {
            const int i = mbase + tid;
            stok[tid] = (i < cnt) ? g_tok[e * NTOK + i] : -1;
        }
    } else {
        if (tid < BM) stok[tid] = mbase + tid;
    }
    __syncthreads();

    const uint32_t sb = smem_u32(smem);

    // ---- cp.async role: arr = tid>>7 (0 Ah, 1 Al, 2 Bh, 3 Bl); 1 row each
    const int arr = tid >> 7;
    const int r0 = tid & 127;
    const __half* gp;
    uint32_t sz;
    if (arr < 2) {
        const __half* base = (arr == 0) ? g_Xh : g_Xl;
        const int tok = stok[r0];
        sz = (tok >= 0) ? 16u : 0u;
        gp = base + (size_t)(tok >= 0 ? tok : 0) * DIM;
    } else {
        const __half* base = ((arr == 2) ? g_Wh : g_Wl) + woff;
        gp = base + (size_t)(nbase + r0) * DIM;
        sz = 16u;
    }
    const uint32_t sdst = sb + arr * ARRB + r0 * ROWB;

    // ---- warp tiling: 16 warps as 4(m) x 4(n); warp tile 32x32
    const int wm = (w & 3) * 32;
    const int wn = (w >> 2) * 32;
    const int lr = lane & 15;
    const int lkb = (lane >> 4) * 16;   // k-half byte offset for ldmatrix

    float acc1[2][4][4];
    float acc2[2][4][4];
    #pragma unroll
    for (int mi = 0; mi < 2; ++mi)
        #pragma unroll
        for (int nj = 0; nj < 4; ++nj)
            #pragma unroll
            for (int q = 0; q < 4; ++q) { acc1[mi][nj][q] = 0.f; acc2[mi][nj][q] = 0.f; }

    // prologue: stages 0 and 1
    #pragma unroll
    for (int s = 0; s < 2; ++s) {
        #pragma unroll
        for (int q = 0; q < 4; ++q)
            CP_ASYNC16(sdst + s * STGB + q * 16, (const char*)(gp + s * BK) + q * 16, sz);
        CP_COMMIT();
    }

    int rd = 0, wr = 2;   // rotating slot indices (mod 3)
    for (int it = 0; it < KIT; ++it) {
        CP_WAIT_1();            // stage `it` complete (stage it+1 may be in flight)
        __syncthreads();        // all warps see it; all done reading slot `wr`

        if (it + 2 < KIT) {     // issue loads for stage it+2 into slot wr
            const uint32_t d = sdst + wr * STGB;
            const int k0 = (it + 2) * BK;
            #pragma unroll
            for (int q = 0; q < 4; ++q)
                CP_ASYNC16(d + q * 16, (const char*)(gp + k0) + q * 16, sz);
        }
        CP_COMMIT();            // always commit (keeps group accounting uniform)

        const uint32_t sgb = sb + rd * STGB;
        #pragma unroll
        for (int kk = 0; kk < 2; ++kk) {       // two k16 steps in BK=32
            const uint32_t kb = kk * 32 + lkb; // byte offset within row
            uint32_t ah[2][4], al[2][4];
            #pragma unroll
            for (int mi = 0; mi < 2; ++mi) {
                const uint32_t rowo = (uint32_t)(wm + mi * 16 + lr) * ROWB + kb;
                LDM_X4(ah[mi], sgb + rowo);            // Ah at arr 0
                LDM_X4(al[mi], sgb + ARRB + rowo);     // Al at arr 1
            }
            #pragma unroll
            for (int njp = 0; njp < 2; ++njp) {
                uint32_t bh[4], bl[4];
                const uint32_t rowo = (uint32_t)(wn + njp * 16 + lr) * ROWB + kb;
                LDM_X4(bh, sgb + 2 * ARRB + rowo);
                LDM_X4(bl, sgb + 3 * ARRB + rowo);
                // pass 1: ah*bh -> acc1 (4 independent MMAs)
                #pragma unroll
                for (int mi = 0; mi < 2; ++mi)
                    #pragma unroll
                    for (int t = 0; t < 2; ++t)
                        MMA(acc1[mi][njp * 2 + t], ah[mi], bh[t], bh[t + 2]);
                // pass 2: ah*bl -> acc2 (4 independent)
                #pragma unroll
                for (int mi = 0; mi < 2; ++mi)
                    #pragma unroll
                    for (int t = 0; t < 2; ++t)
                        MMA(acc2[mi][njp * 2 + t], ah[mi], bl[t], bl[t + 2]);
                // pass 3: al*bh -> acc2 (chained to pass 2, separated by 4 MMAs)
                #pragma unroll
                for (int mi = 0; mi < 2; ++mi)
                    #pragma unroll
                    for (int t = 0; t < 2; ++t)
                        MMA(acc2[mi][njp * 2 + t], al[mi], bh[t], bh[t + 2]);
            }
        }
        rd = (rd == 2) ? 0 : rd + 1;
        wr = (wr == 2) ? 0 : wr + 1;
    }

    // ---- epilogue ----
    const int gid = lane >> 2;
    const int tq = lane & 3;
    #pragma unroll
    for (int mi = 0; mi < 2; ++mi) {
        #pragma unroll
        for (int rh = 0; rh < 2; ++rh) {
            const int mloc = wm + mi * 16 + gid + rh * 8;
            const int tok = stok[mloc];
            if (MODE == 1 && tok < 0) continue;
            const float pt = (MODE == 1) ? g_p[tok] : 1.f;
            float* dst = C + (size_t)tok * DIM;
            #pragma unroll
            for (int nj = 0; nj < 4; ++nj) {
                const int n = nbase + wn + nj * 8 + tq * 2;
                float v0 = (acc1[mi][nj][rh * 2]     + acc2[mi][nj][rh * 2]     * (1.f / 4096.f)) * (1.f / 64.f) + bias[n];
                float v1 = (acc1[mi][nj][rh * 2 + 1] + acc2[mi][nj][rh * 2 + 1] * (1.f / 4096.f)) * (1.f / 64.f) + bias[n + 1];
                if (MODE == 1) {
                    v0 = fmaxf(v0, 0.f) * pt;
                    v1 = fmaxf(v1, 0.f) * pt;
                }
                *(float2*)(dst + n) = make_float2(v0, v1);
            }
        }
    }
}

// =====================================================================
// Routing: 1 block per token; argmax (first-index tie-break) + 1/sum(exp)
// =====================================================================
__global__ __launch_bounds__(256) void k_route() {
    const int t = blockIdx.x;
    const int tid = threadIdx.x;
    const float* row = g_logits + (size_t)t * DIM;

    float4 v = ((const float4*)row)[tid];

    float m = v.x; int mi = tid * 4;
    if (v.y > m) { m = v.y; mi = tid * 4 + 1; }
    if (v.z > m) { m = v.z; mi = tid * 4 + 2; }
    if (v.w > m) { m = v.w; mi = tid * 4 + 3; }

    #pragma unroll
    for (int off = 16; off > 0; off >>= 1) {
        float om = __shfl_down_sync(0xffffffffu, m, off);
        int   oi = __shfl_down_sync(0xffffffffu, mi, off);
        if (om > m || (om == m && oi < mi)) { m = om; mi = oi; }
    }

    __shared__ float sm[8];
    __shared__ int   si[8];
    __shared__ float smax;
    __shared__ int   sarg;

    const int wid = tid >> 5, lane = tid & 31;
    if (lane == 0) { sm[wid] = m; si[wid] = mi; }
    __syncthreads();
    if (tid == 0) {
        float bm_ = sm[0]; int bi = si[0];
        #pragma unroll
        for (int w = 1; w < 8; w++)
            if (sm[w] > bm_ || (sm[w] == bm_ && si[w] < bi)) { bm_ = sm[w]; bi = si[w]; }
        smax = bm_; sarg = bi;
    }
    __syncthreads();

    const float mx = smax;
    float s = expf(v.x - mx) + expf(v.y - mx) + expf(v.z - mx) + expf(v.w - mx);
    #pragma unroll
    for (int off = 16; off > 0; off >>= 1)
        s += __shfl_down_sync(0xffffffffu, s, off);
    if (lane == 0) sm[wid] = s;
    __syncthreads();
    if (tid == 0) {
        float tot = 0.f;
        #pragma unroll
        for (int w = 0; w < 8; w++) tot += sm[w];
        const int ex = sarg & (NEXP - 1);
        const int pos = atomicAdd(&g_cnt[ex], 1);
        g_tok[ex * NTOK + pos] = t;
        g_p[t] = 1.f / tot;
    }
}

// =====================================================================
extern "C" void kernel_launch(void* const* d_in, const int* in_sizes, int n_in,
                              void* d_out, int out_size) {
    const float* x  = (const float*)d_in[0];
    const float* Wg = (const float*)d_in[1];
    const float* bg = (const float*)d_in[2];
    const float* We = (const float*)d_in[3];
    const float* be = (const float*)d_in[4];
    float* out = (float*)d_out;

    float* logits;
    cudaGetSymbolAddress((void**)&logits, g_logits);

    cudaFuncSetAttribute(k_gemm<0>, cudaFuncAttributeMaxDynamicSharedMemorySize, SMEM_BYTES);
    cudaFuncSetAttribute(k_gemm<1>, cudaFuncAttributeMaxDynamicSharedMemorySize, SMEM_BYTES);

    k_init<<<1, 32>>>();
    k_split_x<<<(NTOK * DIM / 4) / 256, 256>>>(x);
    k_split_w<<<dim3(32, 32, 1 + NEXP), dim3(32, 8)>>>(Wg, We);
    k_gemm<0><<<dim3(DIM / BN, NTOK / BM), 512, SMEM_BYTES>>>(bg, logits);
    k_route<<<NTOK, 256>>>();
    k_gemm<1><<<dim3(DIM / BN, NTOK / BM, NEXP), 512, SMEM_BYTES>>>(be, out);
}